// round 12
// baseline (speedup 1.0000x reference)
#include <cuda_runtime.h>
#include <cuda_bf16.h>
#include <math.h>
#include <stdint.h>

#define TT 512
#define BB 256
#define DIN 256
#define DLT 256
#define NCTA 128
#define NGRP 16         // CTAs per barrier group (one 32-row b-tile)

// output layout (floats): H[(T+1),B,DL], C[(T+1),B,DL], F[T,B,DL], I[T,B,DL], O[T,B,DL]
#define H_OFF 0
#define C_OFF ((TT + 1) * BB * DLT)
#define F_OFF (2 * (TT + 1) * BB * DLT)
#define I_OFF (F_OFF + TT * BB * DLT)
#define O_OFF (I_OFF + TT * BB * DLT)

// bf16 hi/lo scratch for X
__device__ __nv_bfloat16 g_Xhi[TT * BB * DIN];
__device__ __nv_bfloat16 g_Xlo[TT * BB * DIN];

// packed h exchange buffer: [parity][hi/lo][row*256+col], reused every 2 steps
__device__ __nv_bfloat16 g_Hp[2][2][BB * DLT];

// per-group barrier state, 128B-separated (8 groups)
__device__ unsigned int g_cnt2[16 * 32];
__device__ unsigned int g_gen2[16 * 32];

__device__ __forceinline__ float sigm(float x) { return 1.0f / (1.0f + expf(-x)); }

__device__ __forceinline__ unsigned int ld_acquire_gpu(const unsigned int* p)
{
    unsigned int v;
    asm volatile("ld.acquire.gpu.global.u32 %0, [%1];" : "=r"(v) : "l"(p) : "memory");
    return v;
}
__device__ __forceinline__ void red_release_add(unsigned int* p, unsigned int v)
{
    asm volatile("red.release.gpu.global.add.u32 [%0], %1;" :: "l"(p), "r"(v) : "memory");
}
__device__ __forceinline__ void group_barrier(int slot, unsigned target)
{
    __syncthreads();
    if (threadIdx.x == 0) {
        __threadfence();
        if (atomicAdd(&g_cnt2[slot], 1) == NGRP - 1) {
            atomicExch(&g_cnt2[slot], 0);
            red_release_add(&g_gen2[slot], 1);
        } else {
            while (ld_acquire_gpu(&g_gen2[slot]) != target) { __nanosleep(32); }
        }
        __threadfence();
    }
    __syncthreads();
}

__device__ __forceinline__ void split2(float x, float y, uint32_t& hi, uint32_t& lo)
{
    __nv_bfloat16 hx = __float2bfloat16(x);
    __nv_bfloat16 hy = __float2bfloat16(y);
    __nv_bfloat16 lx = __float2bfloat16(x - __bfloat162float(hx));
    __nv_bfloat16 ly = __float2bfloat16(y - __bfloat162float(hy));
    __nv_bfloat162 h2 = __halves2bfloat162(hx, hy);
    __nv_bfloat162 l2 = __halves2bfloat162(lx, ly);
    hi = *(uint32_t*)&h2;
    lo = *(uint32_t*)&l2;
}

__device__ __forceinline__ void mma16816(float* d, const uint32_t* a, const uint32_t* b)
{
    asm volatile(
        "mma.sync.aligned.m16n8k16.row.col.f32.bf16.bf16.f32 "
        "{%0,%1,%2,%3}, {%4,%5,%6,%7}, {%8,%9}, {%0,%1,%2,%3};"
        : "+f"(d[0]), "+f"(d[1]), "+f"(d[2]), "+f"(d[3])
        : "r"(a[0]), "r"(a[1]), "r"(a[2]), "r"(a[3]), "r"(b[0]), "r"(b[1]));
}

__device__ __forceinline__ void ldsm4(uint32_t* r, uint32_t addr)
{
    asm volatile("ldmatrix.sync.aligned.m8n8.x4.shared.b16 {%0,%1,%2,%3}, [%4];"
                 : "=r"(r[0]), "=r"(r[1]), "=r"(r[2]), "=r"(r[3]) : "r"(addr));
}

__device__ __forceinline__ void cp16ca(uint32_t saddr, const void* g)
{
    asm volatile("cp.async.ca.shared.global [%0], [%1], 16;" :: "r"(saddr), "l"(g));
}
__device__ __forceinline__ void cp16cg(uint32_t saddr, const void* g)
{
    asm volatile("cp.async.cg.shared.global [%0], [%1], 16;" :: "r"(saddr), "l"(g));
}
__device__ __forceinline__ void cp_commit() { asm volatile("cp.async.commit_group;"); }
template<int N> __device__ __forceinline__ void cp_wait() { asm volatile("cp.async.wait_group %0;" :: "n"(N)); }

// ---------------------------------------------------------------------------
// converter: X fp32 -> bf16 hi/lo, once
// ---------------------------------------------------------------------------
__global__ void __launch_bounds__(256) convX_kernel(const float* __restrict__ X)
{
    int idx = blockIdx.x * 256 + threadIdx.x;
    if (idx < TT * BB * DIN / 4) {
        float4 v = *(const float4*)&X[(size_t)idx * 4];
        uint32_t h01, l01, h23, l23;
        split2(v.x, v.y, h01, l01);
        split2(v.z, v.w, h23, l23);
        ((uint2*)g_Xhi)[idx] = make_uint2(h01, h23);
        ((uint2*)g_Xlo)[idx] = make_uint2(l01, l23);
    }
}

// ---------------------------------------------------------------------------
// fused persistent kernel: the WHOLE problem.
// 128 CTAs = 8 b-tiles (32 rows) x 16 j-tiles (16 j-cols x 4 gates = 64
// gate-cols). Full K=512 weights (Wh|Wx, hi/lo) cached in smem. Per step:
// prefetch X[t] (hides under barrier wait), stage packed h, one mma loop over
// K=512 (3-pass split), +bias, activate, update, publish h, arrive.
// ---------------------------------------------------------------------------
#define PWS 264
#define WH_H 0                       // 64 gc x 264 x 2B = 33792 each
#define WH_L 33792
#define WX_H 67584
#define WX_L 101376
#define HS_H 135168                  // 32 rows x 264 x 2B = 16896 each
#define HS_L 152064
#define XS_H 168960
#define XS_L 185856
#define SG_B 202752                  // float[4*32*18] = 9216
#define CS_B 211968                  // float[512] = 2048
#define PSMEM 214016

__global__ void __launch_bounds__(256) persist_kernel(
    const float* __restrict__ W0, const float* __restrict__ W1,
    const float* __restrict__ W2, const float* __restrict__ W3,
    const float* __restrict__ b0v, const float* __restrict__ b1v,
    const float* __restrict__ b2v, const float* __restrict__ b3v,
    float* __restrict__ out)
{
    extern __shared__ char smem[];
    __nv_bfloat16* whH = (__nv_bfloat16*)(smem + WH_H);
    __nv_bfloat16* whL = (__nv_bfloat16*)(smem + WH_L);
    __nv_bfloat16* wxH = (__nv_bfloat16*)(smem + WX_H);
    __nv_bfloat16* wxL = (__nv_bfloat16*)(smem + WX_L);
    float* sg = (float*)(smem + SG_B);
    float* cs = (float*)(smem + CS_B);
    const uint32_t shb = (uint32_t)__cvta_generic_to_shared(smem);

    const int tid = threadIdx.x;
    const int bt = blockIdx.x >> 4;     // 0..7
    const int jt = blockIdx.x & 15;     // 0..15
    const int b0 = bt * 32;
    const int j0 = jt * 16;
    const int slot = bt * 32;

    __shared__ unsigned s_gen0;
    if (tid == 0) s_gen0 = ld_acquire_gpu(&g_gen2[slot]);

    // ---- load + split FULL weight slice once: 64 gc x 512 k ----
#pragma unroll
    for (int it = 0; it < 32; it++) {
        int idx = tid + it * 256;       // 0..8191 float4
        int gc = idx >> 7;              // 0..63
        int kq = idx & 127;             // float4 col in 512-wide row
        int g  = gc >> 4;
        int jr = j0 + (gc & 15);
        const float* Wg = (g == 0) ? W0 : (g == 1) ? W1 : (g == 2) ? W2 : W3;
        float4 v = *(const float4*)&Wg[(size_t)jr * 512 + kq * 4];
        uint32_t h01, l01, h23, l23;
        split2(v.x, v.y, h01, l01);
        split2(v.z, v.w, h23, l23);
        __nv_bfloat16 *dh, *dl;
        int kc;
        if (kq < 64) { dh = whH; dl = whL; kc = kq * 4; }
        else         { dh = wxH; dl = wxL; kc = (kq - 64) * 4; }
        int base = gc * PWS + kc;
        *(uint32_t*)&dh[base]     = h01;
        *(uint32_t*)&dh[base + 2] = h23;
        *(uint32_t*)&dl[base]     = l01;
        *(uint32_t*)&dl[base + 2] = l23;
    }

    // cell mapping for init/update: 32 rows x 16 cols, 2 cells/thread
    const int cell = tid * 2;
    const int ur  = cell >> 4;          // 0..31
    const int ujl = cell & 15;          // even col within j-tile

    // ---- init: zero c, H0/C0 gmem tiles, Hpack parity 0 ----
    {
        float2 z = make_float2(0.0f, 0.0f);
        *(float2*)&cs[cell] = z;
        *(float2*)&out[H_OFF + (b0 + ur) * DLT + j0 + ujl] = z;
        *(float2*)&out[C_OFF + (b0 + ur) * DLT + j0 + ujl] = z;
        int pos = (b0 + ur) * 256 + j0 + ujl;
        *(uint32_t*)&g_Hp[0][0][pos] = 0u;
        *(uint32_t*)&g_Hp[0][1][pos] = 0u;
    }
    __syncthreads();
    const unsigned base_gen = s_gen0;
    group_barrier(slot, base_gen + 1);

    // warp roles: wm = 16-row half, gate = warp>>1 (16 cols each)
    const int warp = tid >> 5;
    const int lane = tid & 31;
    const int wm = warp & 1;
    const int gate = warp >> 1;
    const int lg = lane >> 2;
    const int tq = lane & 3;
    const int rowsel = lane & 15;
    const int koff   = (lane >> 4) * 8;

    const uint32_t aH = shb + HS_H + ((wm * 16 + rowsel) * PWS + koff) * 2;
    const uint32_t xH = shb + XS_H + ((wm * 16 + rowsel) * PWS + koff) * 2;
    const uint32_t bH = shb + WH_H + ((gate * 16 + rowsel) * PWS + koff) * 2;
    const uint32_t cH = shb + WX_H + ((gate * 16 + rowsel) * PWS + koff) * 2;
    const uint32_t LREL = 16896;        // hs/xs lo offset
    const uint32_t WREL = 33792;        // wh/wx lo offset

    // hoist bias into registers
    const float* bias = (gate == 0) ? b0v : (gate == 1) ? b1v : (gate == 2) ? b2v : b3v;
    float bv[2][2];
#pragma unroll
    for (int j = 0; j < 2; j++) {
        int col = j0 + j * 8 + tq * 2;
        bv[j][0] = bias[col];
        bv[j][1] = bias[col + 1];
    }

    for (int t = 0; t < TT; t++) {
        // ---- X[t] stage (independent of peers; hides under wait) ----
#pragma unroll
        for (int it = 0; it < 8; it++) {
            int idx = tid + it * 256;       // 0..2047
            int hl  = idx >> 10;
            int rem = idx & 1023;
            int r   = rem >> 5;
            int q   = rem & 31;
            uint32_t sa = shb + XS_H + hl * LREL + r * (PWS * 2) + q * 16;
            const __nv_bfloat16* src = (hl ? g_Xlo : g_Xhi) + (t * BB + b0 + r) * 256 + q * 8;
            cp16ca(sa, src);
        }
        cp_commit();

        // ---- wait: h_t published ----
        if (tid == 0) {
            unsigned tgt = base_gen + 1 + (unsigned)t;
            while (ld_acquire_gpu(&g_gen2[slot]) != tgt) { __nanosleep(32); }
        }
        __syncthreads();

        // ---- h stage (L2-only; parity buffer) ----
        {
            const int par = t & 1;
#pragma unroll
            for (int it = 0; it < 8; it++) {
                int idx = tid + it * 256;
                int hl  = idx >> 10;
                int rem = idx & 1023;
                int r   = rem >> 5;
                int q   = rem & 31;
                uint32_t sa = shb + HS_H + hl * LREL + r * (PWS * 2) + q * 16;
                cp16cg(sa, &g_Hp[par][hl][(b0 + r) * 256 + q * 8]);
            }
            cp_commit();
            cp_wait<0>();
        }
        __syncthreads();

        // ---- mma over K=512: h-side then x-side, 3-pass split ----
        float acc[2][4];
#pragma unroll
        for (int j = 0; j < 2; j++)
#pragma unroll
            for (int u = 0; u < 4; u++) acc[j][u] = 0.0f;

#pragma unroll
        for (int k16 = 0; k16 < 256; k16 += 16) {
            uint32_t ah[4], al[4], b4h[4], b4l[4];
            ldsm4(ah,  aH + k16 * 2);
            ldsm4(al,  aH + LREL + k16 * 2);
            ldsm4(b4h, bH + k16 * 2);
            ldsm4(b4l, bH + WREL + k16 * 2);
            uint32_t bh0[2] = { b4h[0], b4h[2] };
            uint32_t bh1[2] = { b4h[1], b4h[3] };
            uint32_t bl0[2] = { b4l[0], b4l[2] };
            uint32_t bl1[2] = { b4l[1], b4l[3] };
            mma16816(acc[0], ah, bh0);
            mma16816(acc[0], ah, bl0);
            mma16816(acc[0], al, bh0);
            mma16816(acc[1], ah, bh1);
            mma16816(acc[1], ah, bl1);
            mma16816(acc[1], al, bh1);
        }
#pragma unroll
        for (int k16 = 0; k16 < 256; k16 += 16) {
            uint32_t ah[4], al[4], b4h[4], b4l[4];
            ldsm4(ah,  xH + k16 * 2);
            ldsm4(al,  xH + LREL + k16 * 2);
            ldsm4(b4h, cH + k16 * 2);
            ldsm4(b4l, cH + WREL + k16 * 2);
            uint32_t bh0[2] = { b4h[0], b4h[2] };
            uint32_t bh1[2] = { b4h[1], b4h[3] };
            uint32_t bl0[2] = { b4l[0], b4l[2] };
            uint32_t bl1[2] = { b4l[1], b4l[3] };
            mma16816(acc[0], ah, bh0);
            mma16816(acc[0], ah, bl0);
            mma16816(acc[0], al, bh0);
            mma16816(acc[1], ah, bh1);
            mma16816(acc[1], ah, bl1);
            mma16816(acc[1], al, bh1);
        }

        // ---- epilogue: +bias, activate -> sg ----
#pragma unroll
        for (int j = 0; j < 2; j++) {
            int jl = j * 8 + tq * 2;
#pragma unroll
            for (int h = 0; h < 2; h++) {
                int row = wm * 16 + lg + h * 8;
                float vx = acc[j][h * 2 + 0] + bv[j][0];
                float vy = acc[j][h * 2 + 1] + bv[j][1];
                float2 r;
                if (gate == 2) { r.x = tanhf(vx); r.y = tanhf(vy); }
                else           { r.x = sigm(vx);  r.y = sigm(vy);  }
                *(float2*)&sg[(gate * 32 + row) * 18 + jl] = r;
            }
        }
        __syncthreads();

        // ---- update: c/h; publish packed h FIRST ----
        float2 fv = *(const float2*)&sg[(0 * 32 + ur) * 18 + ujl];
        float2 iv = *(const float2*)&sg[(1 * 32 + ur) * 18 + ujl];
        float2 cv = *(const float2*)&sg[(2 * 32 + ur) * 18 + ujl];
        float2 ov = *(const float2*)&sg[(3 * 32 + ur) * 18 + ujl];
        float2 cold = *(const float2*)&cs[cell];
        float2 cnew, hnew;
        cnew.x = fv.x * cold.x + iv.x * cv.x;
        cnew.y = fv.y * cold.y + iv.y * cv.y;
        hnew.x = ov.x * tanhf(cnew.x);
        hnew.y = ov.y * tanhf(cnew.y);
        *(float2*)&cs[cell] = cnew;

        {
            uint32_t hi, lo;
            split2(hnew.x, hnew.y, hi, lo);
            int pos = (b0 + ur) * 256 + j0 + ujl;
            *(uint32_t*)&g_Hp[(t + 1) & 1][0][pos] = hi;
            *(uint32_t*)&g_Hp[(t + 1) & 1][1][pos] = lo;
        }
        __syncthreads();

        // ---- arrive (no wait) ----
        if (tid == 0) {
            __threadfence();
            if (atomicAdd(&g_cnt2[slot], 1) == NGRP - 1) {
                atomicExch(&g_cnt2[slot], 0);
                red_release_add(&g_gen2[slot], 1);
            }
        }

        // ---- shadowed tail: gmem outputs ----
        const int mrow = t * BB + b0 + ur;
        const int jgl  = j0 + ujl;
        *(float2*)&out[H_OFF + (mrow + BB) * DLT + jgl] = hnew;
        *(float2*)&out[C_OFF + (mrow + BB) * DLT + jgl] = cnew;
        *(float2*)&out[F_OFF + mrow * DLT + jgl] = fv;
        *(float2*)&out[I_OFF + mrow * DLT + jgl] = iv;
        *(float2*)&out[O_OFF + mrow * DLT + jgl] = ov;
    }
}

// ---------------------------------------------------------------------------
extern "C" void kernel_launch(void* const* d_in, const int* in_sizes, int n_in,
                              void* d_out, int out_size)
{
    const float* X  = (const float*)d_in[0];
    const float* Wf = (const float*)d_in[1];
    const float* bf = (const float*)d_in[2];
    const float* Wi = (const float*)d_in[3];
    const float* bi = (const float*)d_in[4];
    const float* Wc = (const float*)d_in[5];
    const float* bc = (const float*)d_in[6];
    const float* Wo = (const float*)d_in[7];
    const float* bo = (const float*)d_in[8];
    float* out = (float*)d_out;

    cudaFuncSetAttribute(persist_kernel,
                         cudaFuncAttributeMaxDynamicSharedMemorySize, PSMEM);

    convX_kernel<<<TT * BB * DIN / 4 / 256, 256>>>(X);
    persist_kernel<<<NCTA, 256, PSMEM>>>(Wf, Wi, Wc, Wo, bf, bi, bc, bo, out);
}